// round 14
// baseline (speedup 1.0000x reference)
#include <cuda_runtime.h>
#include <math.h>

#define TILE_W    112
#define TILE_H    8
#define HALO      5
#define RAW_W     (TILE_W + 2*HALO)   /* 122 columns incl. halo */
#define VP        123                 /* vs pitch in float4 (mod 8 = 3, odd) */
#define NTHREADS  256
#define VITEMS    (RAW_W * 2)         /* 244 */
#define HITEMS    (TILE_H * (TILE_W/4)) /* 224 */

typedef unsigned long long u64;

// Per-block partial sums (deterministic: each block writes exactly one slot).
__device__ float g_blockSums[65536];
__device__ unsigned int g_count = 0;

// Normalized 1D Gaussian, size 11, sigma 1.5 (matches cv2.getGaussianKernel).
// Used ONLY as compile-time literals -> FFMA-imm (rt_SMSP=1, no banked operands).
__device__ __forceinline__ float gw(int t) {
    constexpr float G[11] = {
        0.00102838f, 0.00759876f, 0.03600077f, 0.10936069f, 0.21300553f,
        0.26601172f,
        0.21300553f, 0.10936069f, 0.03600077f, 0.00759876f, 0.00102838f };
    return G[t];
}

// packed epilogue constants (SCALE = 2^-12 folded; ratio unchanged)
__constant__ float2 cNEG1  = {-1.0f, -1.0f};
__constant__ float2 cTWOS  = {4.8828125e-4f, 4.8828125e-4f};   // 2*2^-12
__constant__ float2 cSCL   = {2.44140625e-4f, 2.44140625e-4f}; // 2^-12
__constant__ float2 cC1S   = {1.58752441e-3f, 1.58752441e-3f}; // 6.5025*2^-12
__constant__ float2 cC2S   = {1.42877197e-2f, 1.42877197e-2f}; // 58.5225*2^-12

__device__ __forceinline__ u64 ldc2(const float2& c) {
    return *reinterpret_cast<const u64*>(&c);
}

// ---- packed f32x2 helpers (epilogue only). pack/unpack are register renames. ----
__device__ __forceinline__ u64 pack2(float lo, float hi) {
    u64 r; asm("mov.b64 %0, {%1, %2};" : "=l"(r) : "f"(lo), "f"(hi)); return r;
}
__device__ __forceinline__ void unpack2(u64 v, float& lo, float& hi) {
    asm("mov.b64 {%0, %1}, %2;" : "=f"(lo), "=f"(hi) : "l"(v));
}
__device__ __forceinline__ u64 mul2(u64 a, u64 b) {
    u64 d; asm("mul.rn.f32x2 %0, %1, %2;" : "=l"(d) : "l"(a), "l"(b)); return d;
}
__device__ __forceinline__ u64 fma2(u64 a, u64 b, u64 c) {
    u64 d; asm("fma.rn.f32x2 %0, %1, %2, %3;" : "=l"(d) : "l"(a), "l"(b), "l"(c)); return d;
}

// Vertical 11-tap blur for one (column, 4-row-group) item, reading gmem directly.
// Scalar FFMA with immediate weights: rt=1/SMSP vs banked fma2's rt=3.
// All pixel offsets fit int32 (4096*4106 < 2^31).
template<bool CLAMP>
__device__ __forceinline__ void vitem(const float* __restrict__ img1,
                                      const float* __restrict__ img2,
                                      int W, int H, int bx, int by, int item,
                                      float4 (*vs)[VP])
{
    const int grp = (item >= RAW_W) ? 1 : 0;
    const int col = item - grp * RAW_W;
    const int r0  = grp * 4;             // output rows r0..r0+3 (tile-local)

    float amu1[4] = {0.f, 0.f, 0.f, 0.f};
    float amu2[4] = {0.f, 0.f, 0.f, 0.f};
    float ass [4] = {0.f, 0.f, 0.f, 0.f};
    float axy [4] = {0.f, 0.f, 0.f, 0.f};

    int gx = bx - HALO + col;
    if (CLAMP) gx = min(max(gx, 0), W - 1);

    int idx = 0;
    if (!CLAMP) idx = (by + r0 - HALO) * W + gx;   // int32 offset

    #pragma unroll
    for (int j = 0; j < 14; j++) {
        float x, y;
        if (CLAMP) {
            int gy = by + r0 - HALO + j;
            gy = min(max(gy, 0), H - 1);
            const int ci = gy * W + gx;
            x = __ldg(img1 + ci);
            y = __ldg(img2 + ci);
        } else {
            x = __ldg(img1 + idx);
            y = __ldg(img2 + idx);
            idx += W;
        }
        const float ss = fmaf(x, x, y * y);    // x^2 + y^2
        const float xy = x * y;
        #pragma unroll
        for (int o = 0; o < 4; o++) {
            const int t = j - o;
            if (t >= 0 && t < 11) {
                amu1[o] = fmaf(x,  gw(t), amu1[o]);
                amu2[o] = fmaf(y,  gw(t), amu2[o]);
                ass [o] = fmaf(ss, gw(t), ass [o]);
                axy [o] = fmaf(xy, gw(t), axy [o]);
            }
        }
    }
    #pragma unroll
    for (int o = 0; o < 4; o++)
        vs[r0 + o][col] = make_float4(amu1[o], amu2[o], ass[o], axy[o]); // STS.128
}

__global__ __launch_bounds__(NTHREADS, 6)
void ssim_tile_kernel(const float* __restrict__ img1,
                      const float* __restrict__ img2,
                      int W, int H, int nBlocks, double inv_n,
                      float* __restrict__ out)
{
    __shared__ float4 vs[TILE_H][VP];   // vertical-blurred (mu1, mu2, ss, xy)
    __shared__ float  wsum[NTHREADS / 32];
    __shared__ bool   isLast;

    const int tid = threadIdx.x;
    const int bx = blockIdx.x * TILE_W;
    const int by = blockIdx.y * TILE_H;

    // ---------------- vertical pass from gmem: 122 cols x 2 row-groups = 244 items ----
    const bool interior = (bx >= HALO) && (by >= HALO) &&
                          (bx + TILE_W + HALO <= W) && (by + TILE_H + HALO <= H);
    if (tid < VITEMS) {
        if (interior) vitem<false>(img1, img2, W, H, bx, by, tid, vs);
        else          vitem<true >(img1, img2, W, H, bx, by, tid, vs);
    }
    __syncthreads();

    // ---------------- horizontal pass + SSIM: 8 rows x 28 groups of 4 cols ----------
    // Lane map: r=tid&7 (pitch 123, 123*r mod 8 distinct) -> conflict-free LDS.128.
    float lsum = 0.f;
    if (tid < HITEMS) {
        const int r  = tid & 7;
        const int g4 = (tid >> 3) << 2;   // output cols g4..g4+3

        float hmu1[4] = {0.f, 0.f, 0.f, 0.f};
        float hmu2[4] = {0.f, 0.f, 0.f, 0.f};
        float hss [4] = {0.f, 0.f, 0.f, 0.f};
        float hxy [4] = {0.f, 0.f, 0.f, 0.f};

        #pragma unroll
        for (int k = 0; k < 14; k++) {
            const float4 v = vs[r][g4 + k];   // LDS.128
            #pragma unroll
            for (int o = 0; o < 4; o++) {
                const int t = k - o;
                if (t >= 0 && t < 11) {
                    hmu1[o] = fmaf(v.x, gw(t), hmu1[o]);
                    hmu2[o] = fmaf(v.y, gw(t), hmu2[o]);
                    hss [o] = fmaf(v.z, gw(t), hss [o]);
                    hxy [o] = fmaf(v.w, gw(t), hxy [o]);
                }
            }
        }

        // ---- packed epilogue: 2 pixels per f32x2 op ----
        const u64 NEG1 = ldc2(cNEG1);
        const u64 TWOS = ldc2(cTWOS);
        const u64 SCL  = ldc2(cSCL);
        const u64 C1S  = ldc2(cC1S);
        const u64 C2S  = ldc2(cC2S);

        float nnv[4], ddv[4];
        #pragma unroll
        for (int p = 0; p < 2; p++) {
            const u64 A   = pack2(hmu1[2*p], hmu1[2*p + 1]);  // (mu1 px0, mu1 px1)
            const u64 B   = pack2(hmu2[2*p], hmu2[2*p + 1]);
            const u64 SQS = pack2(hss [2*p], hss [2*p + 1]);  // G(xx)+G(yy)
            const u64 EXY = pack2(hxy [2*p], hxy [2*p + 1]);  // G(xy)

            const u64 m12  = mul2(A, B);
            const u64 msum = fma2(B, B, mul2(A, A));
            const u64 s12  = fma2(m12,  NEG1, EXY);
            const u64 ssum = fma2(msum, NEG1, SQS);
            const u64 f1 = fma2(m12,  TWOS, C1S);
            const u64 f2 = fma2(s12,  TWOS, C2S);
            const u64 f3 = fma2(msum, SCL,  C1S);
            const u64 f4 = fma2(ssum, SCL,  C2S);
            const u64 nn2 = mul2(f1, f2);
            const u64 dd2 = mul2(f3, f4);
            unpack2(nn2, nnv[2*p], nnv[2*p + 1]);
            unpack2(dd2, ddv[2*p], ddv[2*p + 1]);
        }

        if (!interior) {   // boundary blocks only (≈2.7%): mask invalid pixels
            #pragma unroll
            for (int o = 0; o < 4; o++) {
                const bool valid = (by + r < H) && (bx + g4 + o < W);
                if (!valid) { nnv[o] = 0.f; ddv[o] = 1.f; }
            }
        }

        // sum_i n_i/d_i = (sum_i n_i * prod_{j!=i} d_j) / prod_j d_j -> one RCP / 4 px
        const float d01 = ddv[0] * ddv[1];
        const float d23 = ddv[2] * ddv[3];
        const float D   = d01 * d23;
        const float s01 = fmaf(nnv[0], ddv[1], nnv[1] * ddv[0]);
        const float s23 = fmaf(nnv[2], ddv[3], nnv[3] * ddv[2]);
        const float S   = fmaf(s01, d23, s23 * d01);
        lsum = __fdividef(S, D);
    }

    // ---------------- block reduction ----------------
    #pragma unroll
    for (int off = 16; off; off >>= 1)
        lsum += __shfl_xor_sync(0xffffffffu, lsum, off);
    if ((tid & 31) == 0) wsum[tid >> 5] = lsum;
    __syncthreads();
    if (tid == 0) {
        float s = 0.f;
        #pragma unroll
        for (int w = 0; w < NTHREADS / 32; w++) s += wsum[w];
        g_blockSums[blockIdx.y * gridDim.x + blockIdx.x] = s;
        __threadfence();
        unsigned int prev = atomicAdd(&g_count, 1u);
        isLast = (prev == (unsigned int)(nBlocks - 1));
    }
    __syncthreads();

    // ---------------- last block: final deterministic reduce ----------------
    if (isLast) {
        // reuse vs storage for the double scratch (all vs uses are done)
        double* dsm = reinterpret_cast<double*>(&vs[0][0]);
        double acc = 0.0;
        if ((nBlocks & 3) == 0) {
            const float4* p = (const float4*)g_blockSums;
            const int n4 = nBlocks >> 2;
            for (int i = tid; i < n4; i += NTHREADS) {
                float4 v = p[i];
                acc += (double)v.x + (double)v.y + (double)v.z + (double)v.w;
            }
        } else {
            for (int i = tid; i < nBlocks; i += NTHREADS)
                acc += (double)g_blockSums[i];
        }
        dsm[tid] = acc;
        __syncthreads();
        #pragma unroll
        for (int s = NTHREADS / 2; s; s >>= 1) {
            if (tid < s) dsm[tid] += dsm[tid + s];
            __syncthreads();
        }
        if (tid == 0) {
            out[0] = (float)(dsm[0] * inv_n);
            g_count = 0;   // reset for next graph replay (deterministic)
        }
    }
}

extern "C" void kernel_launch(void* const* d_in, const int* in_sizes, int n_in,
                              void* d_out, int out_size)
{
    (void)n_in; (void)out_size;
    const float* img1 = (const float*)d_in[0];
    const float* img2 = (const float*)d_in[1];

    const long long n = (long long)in_sizes[0];
    int W = (int)(sqrt((double)n) + 0.5);
    if (W <= 0) W = 1;
    int H = (int)(n / W);

    dim3 grid((W + TILE_W - 1) / TILE_W, (H + TILE_H - 1) / TILE_H);
    const int nb = (int)(grid.x * grid.y);
    const double inv_n = 1.0 / ((double)H * (double)W);
    ssim_tile_kernel<<<grid, NTHREADS>>>(img1, img2, W, H, nb, inv_n,
                                         (float*)d_out);
}

// round 15
// speedup vs baseline: 1.2325x; 1.2325x over previous
#include <cuda_runtime.h>
#include <math.h>

#define TILE_W    112
#define TILE_H    16
#define HALO      5
#define RAW_W     (TILE_W + 2*HALO)   /* 122 columns incl. halo */
#define VP        123                 /* vs pitch in float4 (mod 8 = 3, odd) */
#define NTHREADS  256
#define VITEMS    (RAW_W * 2)         /* 244: 2 groups of 8 rows */
#define HITEMS    (TILE_H * (TILE_W/8)) /* 224: 8-col groups */

typedef unsigned long long u64;

// Per-block partial sums (deterministic: each block writes exactly one slot).
__device__ float g_blockSums[65536];
__device__ unsigned int g_count = 0;

// Normalized 1D Gaussian, size 11, sigma 1.5 (matches cv2.getGaussianKernel).
// Used ONLY as compile-time literals -> FFMA-imm (rt_SMSP=1, no banked operands).
__device__ __forceinline__ float gw(int t) {
    constexpr float G[11] = {
        0.00102838f, 0.00759876f, 0.03600077f, 0.10936069f, 0.21300553f,
        0.26601172f,
        0.21300553f, 0.10936069f, 0.03600077f, 0.00759876f, 0.00102838f };
    return G[t];
}

// packed epilogue constants (SCALE = 2^-12 folded; ratio unchanged)
__constant__ float2 cNEG1  = {-1.0f, -1.0f};
__constant__ float2 cTWOS  = {4.8828125e-4f, 4.8828125e-4f};   // 2*2^-12
__constant__ float2 cSCL   = {2.44140625e-4f, 2.44140625e-4f}; // 2^-12
__constant__ float2 cC1S   = {1.58752441e-3f, 1.58752441e-3f}; // 6.5025*2^-12
__constant__ float2 cC2S   = {1.42877197e-2f, 1.42877197e-2f}; // 58.5225*2^-12

__device__ __forceinline__ u64 ldc2(const float2& c) {
    return *reinterpret_cast<const u64*>(&c);
}

// ---- packed f32x2 helpers (epilogue only) ----
__device__ __forceinline__ u64 pack2(float lo, float hi) {
    u64 r; asm("mov.b64 %0, {%1, %2};" : "=l"(r) : "f"(lo), "f"(hi)); return r;
}
__device__ __forceinline__ void unpack2(u64 v, float& lo, float& hi) {
    asm("mov.b64 {%0, %1}, %2;" : "=f"(lo), "=f"(hi) : "l"(v));
}
__device__ __forceinline__ u64 mul2(u64 a, u64 b) {
    u64 d; asm("mul.rn.f32x2 %0, %1, %2;" : "=l"(d) : "l"(a), "l"(b)); return d;
}
__device__ __forceinline__ u64 fma2(u64 a, u64 b, u64 c) {
    u64 d; asm("fma.rn.f32x2 %0, %1, %2, %3;" : "=l"(d) : "l"(a), "l"(b), "l"(c)); return d;
}

// Vertical 11-tap blur: one column x 8 output rows per item, reading gmem.
// 18 rows loaded per 8 outputs (2.25x/px vs 3.5x with 4-row groups).
template<bool CLAMP>
__device__ __forceinline__ void vitem(const float* __restrict__ img1,
                                      const float* __restrict__ img2,
                                      int W, int H, int bx, int by, int item,
                                      float4 (*vs)[VP])
{
    const int grp = (item >= RAW_W) ? 1 : 0;
    const int col = item - grp * RAW_W;
    const int r0  = grp * 8;             // output rows r0..r0+7 (tile-local)

    float amu1[8], amu2[8], ass[8], axy[8];
    #pragma unroll
    for (int o = 0; o < 8; o++) { amu1[o]=0.f; amu2[o]=0.f; ass[o]=0.f; axy[o]=0.f; }

    int gx = bx - HALO + col;
    if (CLAMP) gx = min(max(gx, 0), W - 1);

    int idx = 0;
    if (!CLAMP) idx = (by + r0 - HALO) * W + gx;   // int32 offset

    #pragma unroll
    for (int j = 0; j < 18; j++) {
        float x, y;
        if (CLAMP) {
            int gy = by + r0 - HALO + j;
            gy = min(max(gy, 0), H - 1);
            const int ci = gy * W + gx;
            x = __ldg(img1 + ci);
            y = __ldg(img2 + ci);
        } else {
            x = __ldg(img1 + idx);
            y = __ldg(img2 + idx);
            idx += W;
        }
        const float ss = fmaf(x, x, y * y);    // x^2 + y^2
        const float xy = x * y;
        #pragma unroll
        for (int o = 0; o < 8; o++) {
            const int t = j - o;
            if (t >= 0 && t < 11) {
                amu1[o] = fmaf(x,  gw(t), amu1[o]);
                amu2[o] = fmaf(y,  gw(t), amu2[o]);
                ass [o] = fmaf(ss, gw(t), ass [o]);
                axy [o] = fmaf(xy, gw(t), axy [o]);
            }
        }
    }
    #pragma unroll
    for (int o = 0; o < 8; o++)
        vs[r0 + o][col] = make_float4(amu1[o], amu2[o], ass[o], axy[o]); // STS.128
}

__global__ __launch_bounds__(NTHREADS, 4)
void ssim_tile_kernel(const float* __restrict__ img1,
                      const float* __restrict__ img2,
                      int W, int H, int nBlocks, double inv_n,
                      float* __restrict__ out)
{
    __shared__ float4 vs[TILE_H][VP];   // vertical-blurred (mu1, mu2, ss, xy)
    __shared__ float  wsum[NTHREADS / 32];
    __shared__ bool   isLast;

    const int tid = threadIdx.x;
    const int bx = blockIdx.x * TILE_W;
    const int by = blockIdx.y * TILE_H;

    // -------- vertical pass from gmem: 122 cols x 2 groups of 8 rows = 244 items ----
    const bool interior = (bx >= HALO) && (by >= HALO) &&
                          (bx + TILE_W + HALO <= W) && (by + TILE_H + HALO <= H);
    if (tid < VITEMS) {
        if (interior) vitem<false>(img1, img2, W, H, bx, by, tid, vs);
        else          vitem<true >(img1, img2, W, H, bx, by, tid, vs);
    }
    __syncthreads();

    // -------- horizontal pass + SSIM: 16 rows x 14 groups of 8 cols = 224 items ----
    // Lane map r=tid&15: addr/16 mod 8 = (3r+c) mod 8 -> conflict-free LDS.128 phases.
    float lsum = 0.f;
    if (tid < HITEMS) {
        const int r  = tid & 15;
        const int g8 = (tid >> 4) << 3;   // output cols g8..g8+7

        float hmu1[8], hmu2[8], hss[8], hxy[8];
        #pragma unroll
        for (int o = 0; o < 8; o++) { hmu1[o]=0.f; hmu2[o]=0.f; hss[o]=0.f; hxy[o]=0.f; }

        #pragma unroll
        for (int k = 0; k < 18; k++) {
            const float4 v = vs[r][g8 + k];   // LDS.128
            #pragma unroll
            for (int o = 0; o < 8; o++) {
                const int t = k - o;
                if (t >= 0 && t < 11) {
                    hmu1[o] = fmaf(v.x, gw(t), hmu1[o]);
                    hmu2[o] = fmaf(v.y, gw(t), hmu2[o]);
                    hss [o] = fmaf(v.z, gw(t), hss [o]);
                    hxy [o] = fmaf(v.w, gw(t), hxy [o]);
                }
            }
        }

        // ---- packed epilogue: 2 pixels per f32x2 op ----
        const u64 NEG1 = ldc2(cNEG1);
        const u64 TWOS = ldc2(cTWOS);
        const u64 SCL  = ldc2(cSCL);
        const u64 C1S  = ldc2(cC1S);
        const u64 C2S  = ldc2(cC2S);

        float nnv[8], ddv[8];
        #pragma unroll
        for (int p = 0; p < 4; p++) {
            const u64 A   = pack2(hmu1[2*p], hmu1[2*p + 1]);
            const u64 B   = pack2(hmu2[2*p], hmu2[2*p + 1]);
            const u64 SQS = pack2(hss [2*p], hss [2*p + 1]);
            const u64 EXY = pack2(hxy [2*p], hxy [2*p + 1]);

            const u64 m12  = mul2(A, B);
            const u64 msum = fma2(B, B, mul2(A, A));
            const u64 s12  = fma2(m12,  NEG1, EXY);
            const u64 ssum = fma2(msum, NEG1, SQS);
            const u64 f1 = fma2(m12,  TWOS, C1S);
            const u64 f2 = fma2(s12,  TWOS, C2S);
            const u64 f3 = fma2(msum, SCL,  C1S);
            const u64 f4 = fma2(ssum, SCL,  C2S);
            const u64 nn2 = mul2(f1, f2);
            const u64 dd2 = mul2(f3, f4);
            unpack2(nn2, nnv[2*p], nnv[2*p + 1]);
            unpack2(dd2, ddv[2*p], ddv[2*p + 1]);
        }

        if (!interior) {   // boundary blocks only: mask invalid pixels
            #pragma unroll
            for (int o = 0; o < 8; o++) {
                const bool valid = (by + r < H) && (bx + g8 + o < W);
                if (!valid) { nnv[o] = 0.f; ddv[o] = 1.f; }
            }
        }

        // two rational combines (one RCP per 4 px, as before)
        #pragma unroll
        for (int q = 0; q < 2; q++) {
            const float* nn = nnv + 4*q;
            const float* dd = ddv + 4*q;
            const float d01 = dd[0] * dd[1];
            const float d23 = dd[2] * dd[3];
            const float D   = d01 * d23;
            const float s01 = fmaf(nn[0], dd[1], nn[1] * dd[0]);
            const float s23 = fmaf(nn[2], dd[3], nn[3] * dd[2]);
            const float S   = fmaf(s01, d23, s23 * d01);
            lsum += __fdividef(S, D);
        }
    }

    // ---------------- block reduction ----------------
    #pragma unroll
    for (int off = 16; off; off >>= 1)
        lsum += __shfl_xor_sync(0xffffffffu, lsum, off);
    if ((tid & 31) == 0) wsum[tid >> 5] = lsum;
    __syncthreads();
    if (tid == 0) {
        float s = 0.f;
        #pragma unroll
        for (int w = 0; w < NTHREADS / 32; w++) s += wsum[w];
        g_blockSums[blockIdx.y * gridDim.x + blockIdx.x] = s;
        __threadfence();
        unsigned int prev = atomicAdd(&g_count, 1u);
        isLast = (prev == (unsigned int)(nBlocks - 1));
    }
    __syncthreads();

    // ---------------- last block: final deterministic reduce ----------------
    if (isLast) {
        double* dsm = reinterpret_cast<double*>(&vs[0][0]);
        double acc = 0.0;
        if ((nBlocks & 3) == 0) {
            const float4* p = (const float4*)g_blockSums;
            const int n4 = nBlocks >> 2;
            for (int i = tid; i < n4; i += NTHREADS) {
                float4 v = p[i];
                acc += (double)v.x + (double)v.y + (double)v.z + (double)v.w;
            }
        } else {
            for (int i = tid; i < nBlocks; i += NTHREADS)
                acc += (double)g_blockSums[i];
        }
        dsm[tid] = acc;
        __syncthreads();
        #pragma unroll
        for (int s = NTHREADS / 2; s; s >>= 1) {
            if (tid < s) dsm[tid] += dsm[tid + s];
            __syncthreads();
        }
        if (tid == 0) {
            out[0] = (float)(dsm[0] * inv_n);
            g_count = 0;   // reset for next graph replay (deterministic)
        }
    }
}

extern "C" void kernel_launch(void* const* d_in, const int* in_sizes, int n_in,
                              void* d_out, int out_size)
{
    (void)n_in; (void)out_size;
    const float* img1 = (const float*)d_in[0];
    const float* img2 = (const float*)d_in[1];

    const long long n = (long long)in_sizes[0];
    int W = (int)(sqrt((double)n) + 0.5);
    if (W <= 0) W = 1;
    int H = (int)(n / W);

    dim3 grid((W + TILE_W - 1) / TILE_W, (H + TILE_H - 1) / TILE_H);
    const int nb = (int)(grid.x * grid.y);
    const double inv_n = 1.0 / ((double)H * (double)W);
    ssim_tile_kernel<<<grid, NTHREADS>>>(img1, img2, W, H, nb, inv_n,
                                         (float*)d_out);
}

// round 16
// speedup vs baseline: 1.2334x; 1.0007x over previous
#include <cuda_runtime.h>
#include <math.h>

#define TILE_W    112
#define TILE_H    16
#define HALO      5
#define RAW_W     (TILE_W + 2*HALO)   /* 122 columns incl. halo */
#define VP        123                 /* vs pitch in float4 (mod 8 = 3, odd) */
#define NTHREADS  256
#define VITEMS    (RAW_W * 2)         /* 244: 2 groups of 8 rows */
#define HITEMS    (TILE_H * (TILE_W/7)) /* 256: 7-col groups, exact fit */

typedef unsigned long long u64;

// Per-block partial sums (deterministic: each block writes exactly one slot).
__device__ float g_blockSums[65536];
__device__ unsigned int g_count = 0;

// Normalized 1D Gaussian, size 11, sigma 1.5 (matches cv2.getGaussianKernel).
// Used ONLY as compile-time literals -> FFMA-imm (rt_SMSP=1, no banked operands).
__device__ __forceinline__ float gw(int t) {
    constexpr float G[11] = {
        0.00102838f, 0.00759876f, 0.03600077f, 0.10936069f, 0.21300553f,
        0.26601172f,
        0.21300553f, 0.10936069f, 0.03600077f, 0.00759876f, 0.00102838f };
    return G[t];
}

// packed epilogue constants (SCALE = 2^-12 folded; ratio unchanged)
__constant__ float2 cNEG1  = {-1.0f, -1.0f};
__constant__ float2 cTWOS  = {4.8828125e-4f, 4.8828125e-4f};   // 2*2^-12
__constant__ float2 cSCL   = {2.44140625e-4f, 2.44140625e-4f}; // 2^-12
__constant__ float2 cC1S   = {1.58752441e-3f, 1.58752441e-3f}; // 6.5025*2^-12
__constant__ float2 cC2S   = {1.42877197e-2f, 1.42877197e-2f}; // 58.5225*2^-12

__device__ __forceinline__ u64 ldc2(const float2& c) {
    return *reinterpret_cast<const u64*>(&c);
}

// ---- packed f32x2 helpers (epilogue only) ----
__device__ __forceinline__ u64 pack2(float lo, float hi) {
    u64 r; asm("mov.b64 %0, {%1, %2};" : "=l"(r) : "f"(lo), "f"(hi)); return r;
}
__device__ __forceinline__ void unpack2(u64 v, float& lo, float& hi) {
    asm("mov.b64 {%0, %1}, %2;" : "=f"(lo), "=f"(hi) : "l"(v));
}
__device__ __forceinline__ u64 mul2(u64 a, u64 b) {
    u64 d; asm("mul.rn.f32x2 %0, %1, %2;" : "=l"(d) : "l"(a), "l"(b)); return d;
}
__device__ __forceinline__ u64 fma2(u64 a, u64 b, u64 c) {
    u64 d; asm("fma.rn.f32x2 %0, %1, %2, %3;" : "=l"(d) : "l"(a), "l"(b), "l"(c)); return d;
}

// Vertical 11-tap blur: one column x 8 output rows per item, reading gmem.
// 18 rows loaded per 8 outputs.
template<bool CLAMP>
__device__ __forceinline__ void vitem(const float* __restrict__ img1,
                                      const float* __restrict__ img2,
                                      int W, int H, int bx, int by, int item,
                                      float4 (*vs)[VP])
{
    const int grp = (item >= RAW_W) ? 1 : 0;
    const int col = item - grp * RAW_W;
    const int r0  = grp * 8;             // output rows r0..r0+7 (tile-local)

    float amu1[8], amu2[8], ass[8], axy[8];
    #pragma unroll
    for (int o = 0; o < 8; o++) { amu1[o]=0.f; amu2[o]=0.f; ass[o]=0.f; axy[o]=0.f; }

    int gx = bx - HALO + col;
    if (CLAMP) gx = min(max(gx, 0), W - 1);

    int idx = 0;
    if (!CLAMP) idx = (by + r0 - HALO) * W + gx;   // int32 offset

    #pragma unroll
    for (int j = 0; j < 18; j++) {
        float x, y;
        if (CLAMP) {
            int gy = by + r0 - HALO + j;
            gy = min(max(gy, 0), H - 1);
            const int ci = gy * W + gx;
            x = __ldg(img1 + ci);
            y = __ldg(img2 + ci);
        } else {
            x = __ldg(img1 + idx);
            y = __ldg(img2 + idx);
            idx += W;
        }
        const float ss = fmaf(x, x, y * y);    // x^2 + y^2
        const float xy = x * y;
        #pragma unroll
        for (int o = 0; o < 8; o++) {
            const int t = j - o;
            if (t >= 0 && t < 11) {
                amu1[o] = fmaf(x,  gw(t), amu1[o]);
                amu2[o] = fmaf(y,  gw(t), amu2[o]);
                ass [o] = fmaf(ss, gw(t), ass [o]);
                axy [o] = fmaf(xy, gw(t), axy [o]);
            }
        }
    }
    #pragma unroll
    for (int o = 0; o < 8; o++)
        vs[r0 + o][col] = make_float4(amu1[o], amu2[o], ass[o], axy[o]); // STS.128
}

__global__ __launch_bounds__(NTHREADS, 4)
void ssim_tile_kernel(const float* __restrict__ img1,
                      const float* __restrict__ img2,
                      int W, int H, int nBlocks, double inv_n,
                      float* __restrict__ out)
{
    __shared__ float4 vs[TILE_H][VP];   // vertical-blurred (mu1, mu2, ss, xy)
    __shared__ float  wsum[NTHREADS / 32];
    __shared__ bool   isLast;

    const int tid = threadIdx.x;
    const int bx = blockIdx.x * TILE_W;
    const int by = blockIdx.y * TILE_H;

    // -------- vertical pass from gmem: 122 cols x 2 groups of 8 rows = 244 items ----
    const bool interior = (bx >= HALO) && (by >= HALO) &&
                          (bx + TILE_W + HALO <= W) && (by + TILE_H + HALO <= H);
    if (tid < VITEMS) {
        if (interior) vitem<false>(img1, img2, W, H, bx, by, tid, vs);
        else          vitem<true >(img1, img2, W, H, bx, by, tid, vs);
    }
    __syncthreads();

    // -------- horizontal pass + SSIM: 16 rows x 16 groups of 7 cols = 256 items ----
    // Lane map r=tid&15: addr/16 mod 8 = (3r+c) mod 8; 8-lane phases share c,
    // distinct r -> conflict-free LDS.128.
    float lsum = 0.f;
    {
        const int r  = tid & 15;
        const int g7 = (tid >> 4) * 7;   // output cols g7..g7+6

        float hmu1[7], hmu2[7], hss[7], hxy[7];
        #pragma unroll
        for (int o = 0; o < 7; o++) { hmu1[o]=0.f; hmu2[o]=0.f; hss[o]=0.f; hxy[o]=0.f; }

        #pragma unroll
        for (int k = 0; k < 17; k++) {
            const float4 v = vs[r][g7 + k];   // LDS.128
            #pragma unroll
            for (int o = 0; o < 7; o++) {
                const int t = k - o;
                if (t >= 0 && t < 11) {
                    hmu1[o] = fmaf(v.x, gw(t), hmu1[o]);
                    hmu2[o] = fmaf(v.y, gw(t), hmu2[o]);
                    hss [o] = fmaf(v.z, gw(t), hss [o]);
                    hxy [o] = fmaf(v.w, gw(t), hxy [o]);
                }
            }
        }

        // ---- epilogue: 3 packed pixel-pairs + 1 scalar pixel ----
        const u64 NEG1 = ldc2(cNEG1);
        const u64 TWOS = ldc2(cTWOS);
        const u64 SCL  = ldc2(cSCL);
        const u64 C1S  = ldc2(cC1S);
        const u64 C2S  = ldc2(cC2S);

        float nnv[7], ddv[7];
        #pragma unroll
        for (int p = 0; p < 3; p++) {
            const u64 A   = pack2(hmu1[2*p], hmu1[2*p + 1]);
            const u64 B   = pack2(hmu2[2*p], hmu2[2*p + 1]);
            const u64 SQS = pack2(hss [2*p], hss [2*p + 1]);
            const u64 EXY = pack2(hxy [2*p], hxy [2*p + 1]);

            const u64 m12  = mul2(A, B);
            const u64 msum = fma2(B, B, mul2(A, A));
            const u64 s12  = fma2(m12,  NEG1, EXY);
            const u64 ssum = fma2(msum, NEG1, SQS);
            const u64 f1 = fma2(m12,  TWOS, C1S);
            const u64 f2 = fma2(s12,  TWOS, C2S);
            const u64 f3 = fma2(msum, SCL,  C1S);
            const u64 f4 = fma2(ssum, SCL,  C2S);
            const u64 nn2 = mul2(f1, f2);
            const u64 dd2 = mul2(f3, f4);
            unpack2(nn2, nnv[2*p], nnv[2*p + 1]);
            unpack2(dd2, ddv[2*p], ddv[2*p + 1]);
        }
        {   // scalar 7th pixel (constants fold to FFMA-imm)
            const float mu1 = hmu1[6], mu2 = hmu2[6];
            const float m12  = mu1 * mu2;
            const float msum = fmaf(mu1, mu1, mu2 * mu2);
            const float s12  = hxy[6] - m12;
            const float ssum = hss[6] - msum;
            nnv[6] = fmaf(m12,  4.8828125e-4f, 1.58752441e-3f) *
                     fmaf(s12,  4.8828125e-4f, 1.42877197e-2f);
            ddv[6] = fmaf(msum, 2.44140625e-4f, 1.58752441e-3f) *
                     fmaf(ssum, 2.44140625e-4f, 1.42877197e-2f);
        }

        if (!interior) {   // boundary blocks only: mask invalid pixels
            #pragma unroll
            for (int o = 0; o < 7; o++) {
                const bool valid = (by + r < H) && (bx + g7 + o < W);
                if (!valid) { nnv[o] = 0.f; ddv[o] = 1.f; }
            }
        }

        // rational combines: one RCP per 4 px + one per 3 px
        {
            const float d01 = ddv[0] * ddv[1];
            const float d23 = ddv[2] * ddv[3];
            const float D   = d01 * d23;
            const float s01 = fmaf(nnv[0], ddv[1], nnv[1] * ddv[0]);
            const float s23 = fmaf(nnv[2], ddv[3], nnv[3] * ddv[2]);
            const float S   = fmaf(s01, d23, s23 * d01);
            lsum = __fdividef(S, D);
        }
        {
            const float e56 = ddv[5] * ddv[6];
            const float e46 = ddv[4] * ddv[6];
            const float e45 = ddv[4] * ddv[5];
            const float S3  = fmaf(nnv[4], e56, fmaf(nnv[5], e46, nnv[6] * e45));
            const float D3  = ddv[4] * e56;
            lsum += __fdividef(S3, D3);
        }
    }

    // ---------------- block reduction ----------------
    #pragma unroll
    for (int off = 16; off; off >>= 1)
        lsum += __shfl_xor_sync(0xffffffffu, lsum, off);
    if ((tid & 31) == 0) wsum[tid >> 5] = lsum;
    __syncthreads();
    if (tid == 0) {
        float s = 0.f;
        #pragma unroll
        for (int w = 0; w < NTHREADS / 32; w++) s += wsum[w];
        g_blockSums[blockIdx.y * gridDim.x + blockIdx.x] = s;
        __threadfence();
        unsigned int prev = atomicAdd(&g_count, 1u);
        isLast = (prev == (unsigned int)(nBlocks - 1));
    }
    __syncthreads();

    // ---------------- last block: final deterministic reduce ----------------
    if (isLast) {
        double* dsm = reinterpret_cast<double*>(&vs[0][0]);
        double acc = 0.0;
        if ((nBlocks & 3) == 0) {
            const float4* p = (const float4*)g_blockSums;
            const int n4 = nBlocks >> 2;
            for (int i = tid; i < n4; i += NTHREADS) {
                float4 v = p[i];
                acc += (double)v.x + (double)v.y + (double)v.z + (double)v.w;
            }
        } else {
            for (int i = tid; i < nBlocks; i += NTHREADS)
                acc += (double)g_blockSums[i];
        }
        dsm[tid] = acc;
        __syncthreads();
        #pragma unroll
        for (int s = NTHREADS / 2; s; s >>= 1) {
            if (tid < s) dsm[tid] += dsm[tid + s];
            __syncthreads();
        }
        if (tid == 0) {
            out[0] = (float)(dsm[0] * inv_n);
            g_count = 0;   // reset for next graph replay (deterministic)
        }
    }
}

extern "C" void kernel_launch(void* const* d_in, const int* in_sizes, int n_in,
                              void* d_out, int out_size)
{
    (void)n_in; (void)out_size;
    const float* img1 = (const float*)d_in[0];
    const float* img2 = (const float*)d_in[1];

    const long long n = (long long)in_sizes[0];
    int W = (int)(sqrt((double)n) + 0.5);
    if (W <= 0) W = 1;
    int H = (int)(n / W);

    dim3 grid((W + TILE_W - 1) / TILE_W, (H + TILE_H - 1) / TILE_H);
    const int nb = (int)(grid.x * grid.y);
    const double inv_n = 1.0 / ((double)H * (double)W);
    ssim_tile_kernel<<<grid, NTHREADS>>>(img1, img2, W, H, nb, inv_n,
                                         (float*)d_out);
}